// round 14
// baseline (speedup 1.0000x reference)
#include <cuda_runtime.h>
#include <cuda_bf16.h>
#include <cstdint>

#define N_NODES 65536
#define N_EDGES 1048576
#define IN_F 64
#define OUT_F 64

#define SCAN_BLOCKS 64          // 64 blocks x 256 threads x 4 counts = 65536

// ---- scratch (static __device__, 16B-aligned, no allocation) ----
__device__ __align__(16) float g_support[(size_t)N_NODES * OUT_F];  // 16 MB
__device__ __align__(16) uint2 g_sorted[N_EDGES + 8];               // 8 MB + pad
__device__ __align__(16) int   g_counts[N_NODES];
__device__ __align__(16) int   g_rowptr[N_NODES];
__device__ __align__(16) int   g_cursor[N_NODES];
__device__ __align__(16) int   g_blocksums[SCAN_BLOCKS];

// ---------------------------------------------------------------------------
// support = X @ W   (one thread per row, W broadcast from smem)
// ---------------------------------------------------------------------------
__global__ void __launch_bounds__(256)
gemm_kernel(const float* __restrict__ X, const float* __restrict__ W,
            float* __restrict__ S, int n_nodes)
{
    __shared__ float sW[IN_F * OUT_F];
    for (int i = threadIdx.x; i < IN_F * OUT_F; i += 256)
        sW[i] = W[i];
    __syncthreads();

    int row = blockIdx.x * 256 + threadIdx.x;
    if (row >= n_nodes) return;

    float acc[OUT_F];
#pragma unroll
    for (int j = 0; j < OUT_F; j++) acc[j] = 0.0f;

    const float4* xr = reinterpret_cast<const float4*>(X + (size_t)row * IN_F);
#pragma unroll 4
    for (int k4 = 0; k4 < IN_F / 4; k4++) {
        float4 x = xr[k4];
        int k = k4 * 4;
        const float4* w0 = reinterpret_cast<const float4*>(sW + (k + 0) * OUT_F);
        const float4* w1 = reinterpret_cast<const float4*>(sW + (k + 1) * OUT_F);
        const float4* w2 = reinterpret_cast<const float4*>(sW + (k + 2) * OUT_F);
        const float4* w3 = reinterpret_cast<const float4*>(sW + (k + 3) * OUT_F);
#pragma unroll
        for (int j4 = 0; j4 < OUT_F / 4; j4++) {
            float4 a = w0[j4], b = w1[j4], c = w2[j4], d = w3[j4];
            acc[j4 * 4 + 0] += x.x * a.x + x.y * b.x + x.z * c.x + x.w * d.x;
            acc[j4 * 4 + 1] += x.x * a.y + x.y * b.y + x.z * c.y + x.w * d.y;
            acc[j4 * 4 + 2] += x.x * a.z + x.y * b.z + x.z * c.z + x.w * d.z;
            acc[j4 * 4 + 3] += x.x * a.w + x.y * b.w + x.z * c.w + x.w * d.w;
        }
    }

    float4* sr = reinterpret_cast<float4*>(S + (size_t)row * OUT_F);
#pragma unroll
    for (int j4 = 0; j4 < OUT_F / 4; j4++)
        sr[j4] = make_float4(acc[j4*4+0], acc[j4*4+1], acc[j4*4+2], acc[j4*4+3]);
}

// ---------------------------------------------------------------------------
// zero degree counters (also zeroes the sorted-array pad once per call)
// ---------------------------------------------------------------------------
__global__ void __launch_bounds__(256)
zero_counts_kernel(int* __restrict__ counts, uint2* __restrict__ sorted_pad,
                   int n)
{
    int i = blockIdx.x * 256 + threadIdx.x;
    if (i < n) counts[i] = 0;
    if (blockIdx.x == 0 && threadIdx.x < 8)
        sorted_pad[threadIdx.x] = make_uint2(0u, 0u);
}

// ---------------------------------------------------------------------------
// histogram of destination rows
// ---------------------------------------------------------------------------
__global__ void __launch_bounds__(256)
hist_kernel(const int* __restrict__ rows, int* __restrict__ counts, int n_edges)
{
    int e = blockIdx.x * 256 + threadIdx.x;
    if (e < n_edges) atomicAdd(&counts[rows[e]], 1);
}

// ---------------------------------------------------------------------------
// scan phase A: 64 blocks; each reduces its 1024 counts to one block sum
// ---------------------------------------------------------------------------
__global__ void __launch_bounds__(256)
scan_a_kernel(const int* __restrict__ counts, int* __restrict__ blocksums)
{
    __shared__ int sred[256];
    int t = threadIdx.x;
    int4 c = reinterpret_cast<const int4*>(counts)[blockIdx.x * 256 + t];
    int s = c.x + c.y + c.z + c.w;
    sred[t] = s;
    __syncthreads();
    for (int d = 128; d > 0; d >>= 1) {
        if (t < d) sred[t] += sred[t + d];
        __syncthreads();
    }
    if (t == 0) blocksums[blockIdx.x] = sred[0];
}

// ---------------------------------------------------------------------------
// scan phase C (B folded in): each block computes its global offset from the
// 64 L2-resident block sums, then block-local exclusive scan; emits
// rowptr and cursor.
// ---------------------------------------------------------------------------
__global__ void __launch_bounds__(256)
scan_c_kernel(const int* __restrict__ counts, const int* __restrict__ blocksums,
              int* __restrict__ rowptr, int* __restrict__ cursor)
{
    __shared__ int ssum[256];
    __shared__ int sboff;
    int t = threadIdx.x;
    int gidx = blockIdx.x * 256 + t;

    // fold scan_b: sum of blocksums[0..bid) via in-block reduction
    int part = (t < 64 && t < blockIdx.x) ? blocksums[t] : 0;
    ssum[t] = part;
    __syncthreads();
    for (int d = 128; d > 0; d >>= 1) {
        if (t < d) ssum[t] += ssum[t + d];
        __syncthreads();
    }
    if (t == 0) sboff = ssum[0];
    __syncthreads();
    int boff = sboff;
    __syncthreads();

    int4 c = reinterpret_cast<const int4*>(counts)[gidx];
    int s = c.x + c.y + c.z + c.w;
    ssum[t] = s;
    __syncthreads();
    for (int d = 1; d < 256; d <<= 1) {
        int add = (t >= d) ? ssum[t - d] : 0;
        __syncthreads();
        ssum[t] += add;
        __syncthreads();
    }
    int run = boff + ssum[t] - s;  // global exclusive prefix

    int4 o;
    o.x = run; run += c.x;
    o.y = run; run += c.y;
    o.z = run; run += c.z;
    o.w = run; run += c.w;
    reinterpret_cast<int4*>(rowptr)[gidx] = o;
    reinterpret_cast<int4*>(cursor)[gidx] = o;
}

// ---------------------------------------------------------------------------
// place each edge into its dest bucket (cursor-atomic, proven)
// ---------------------------------------------------------------------------
__global__ void __launch_bounds__(256)
place_kernel(const int* __restrict__ rows, const int* __restrict__ cols,
             const float* __restrict__ vals, int* __restrict__ cursor,
             uint2* __restrict__ sorted, int n_edges)
{
    int e = blockIdx.x * 256 + threadIdx.x;
    if (e >= n_edges) return;
    int r = rows[e];
    int pos = atomicAdd(&cursor[r], 1);
    sorted[pos] = make_uint2((unsigned)cols[e], __float_as_uint(vals[e]));
}

// ---------------------------------------------------------------------------
// Gather v4: ONE WARP PER NODE, batch 8 + prefetch 8.
// Lane owns one float2 (32 lanes = 256B row). Edge loads are warp-uniform.
// 8 independent row gathers in flight per batch while the next 8 edge
// records load. Value predication (v=0 on padded slots); gathered col is
// masked with N_NODES-1 and start/deg clamped -> provably in-bounds.
// Single non-atomic write of relu(acc + bias) per lane.
// ---------------------------------------------------------------------------
__global__ void __launch_bounds__(256)
gather_kernel(const int* __restrict__ rowptr, const int* __restrict__ counts,
              const uint2* __restrict__ sorted, const float* __restrict__ S,
              const float* __restrict__ bias, float* __restrict__ out,
              int n_nodes)
{
    int node = (blockIdx.x * 256 + threadIdx.x) >> 5;
    if (node >= n_nodes) return;
    int lane = threadIdx.x & 31;

    int start = rowptr[node];
    int deg   = counts[node];

    // defensive clamps: gather can never read outside sorted[] / S[]
    if (start < 0) start = 0;
    if (start > N_EDGES) start = N_EDGES;
    if (deg < 0) deg = 0;
    if (deg > N_EDGES - start) deg = N_EDGES - start;

    const uint2*  ep = sorted + start;
    const float2* S2 = reinterpret_cast<const float2*>(S);

    float2 acc = make_float2(0.f, 0.f);
    int nb = (deg + 7) >> 3;

    uint2 a[8];
#pragma unroll
    for (int i = 0; i < 8; i++)
        a[i] = (i < deg) ? ep[i] : make_uint2(0u, 0u);

    for (int b = 0; b < nb; b++) {
        // 8 independent 256B row gathers in flight
        float2 s[8];
#pragma unroll
        for (int i = 0; i < 8; i++)
            s[i] = S2[(size_t)(a[i].x & (N_NODES - 1)) * 32 + lane];

        // prefetch next batch of 8 edge records
        int nxt = (b + 1) * 8;
        uint2 n8[8];
#pragma unroll
        for (int i = 0; i < 8; i++)
            n8[i] = (nxt + i < deg) ? ep[nxt + i] : make_uint2(0u, 0u);

#pragma unroll
        for (int i = 0; i < 8; i++) {
            float v = __uint_as_float(a[i].y);
            acc.x += v * s[i].x;
            acc.y += v * s[i].y;
        }

#pragma unroll
        for (int i = 0; i < 8; i++) a[i] = n8[i];
    }

    float2 bb = reinterpret_cast<const float2*>(bias)[lane];
    float2 r;
    r.x = fmaxf(acc.x + bb.x, 0.f);
    r.y = fmaxf(acc.y + bb.y, 0.f);
    reinterpret_cast<float2*>(out)[(size_t)node * 32 + lane] = r;
}

extern "C" void kernel_launch(void* const* d_in, const int* in_sizes, int n_in,
                              void* d_out, int out_size)
{
    const float* X    = (const float*)d_in[0];
    const int*   rows = (const int*)  d_in[1];
    const int*   cols = (const int*)  d_in[2];
    const float* vals = (const float*)d_in[3];
    const float* W    = (const float*)d_in[4];
    const float* bias = (const float*)d_in[5];
    float*       out  = (float*)d_out;

    int n_nodes = in_sizes[0] / IN_F;
    int n_edges = in_sizes[1];

    float* S;      cudaGetSymbolAddress((void**)&S,      g_support);
    uint2* sorted; cudaGetSymbolAddress((void**)&sorted, g_sorted);
    int*   counts; cudaGetSymbolAddress((void**)&counts, g_counts);
    int*   rowptr; cudaGetSymbolAddress((void**)&rowptr, g_rowptr);
    int*   cursor; cudaGetSymbolAddress((void**)&cursor, g_cursor);
    int*   bsums;  cudaGetSymbolAddress((void**)&bsums,  g_blocksums);

    // Side stream + events for gemm overlap (capture-legal fork/join).
    static cudaStream_t s_gemm = nullptr;
    static cudaEvent_t  ev_fork = nullptr, ev_done = nullptr;
    if (s_gemm == nullptr) {
        cudaStreamCreateWithFlags(&s_gemm, cudaStreamNonBlocking);
        cudaEventCreateWithFlags(&ev_fork, cudaEventDisableTiming);
        cudaEventCreateWithFlags(&ev_done, cudaEventDisableTiming);
    }

    // Fork: gemm on the side stream, overlapped with the CSR build.
    cudaEventRecord(ev_fork, 0);
    cudaStreamWaitEvent(s_gemm, ev_fork, 0);
    gemm_kernel<<<(n_nodes + 255) / 256, 256, 0, s_gemm>>>(X, W, S, n_nodes);
    cudaEventRecord(ev_done, s_gemm);

    // CSR build on the main stream.
    zero_counts_kernel<<<(n_nodes + 255) / 256, 256>>>(counts, sorted + N_EDGES,
                                                       n_nodes);
    hist_kernel<<<(n_edges + 255) / 256, 256>>>(rows, counts, n_edges);
    scan_a_kernel<<<SCAN_BLOCKS, 256>>>(counts, bsums);
    scan_c_kernel<<<SCAN_BLOCKS, 256>>>(counts, bsums, rowptr, cursor);
    place_kernel<<<(n_edges + 255) / 256, 256>>>(rows, cols, vals, cursor,
                                                 sorted, n_edges);

    // Join: gather needs both the CSR and the support matrix.
    cudaStreamWaitEvent(0, ev_done, 0);
    long long total = (long long)n_nodes * 32;
    gather_kernel<<<(int)((total + 255) / 256), 256>>>(rowptr, counts, sorted,
                                                       S, bias, out, n_nodes);
}

// round 16
// speedup vs baseline: 1.1017x; 1.1017x over previous
#include <cuda_runtime.h>
#include <cuda_bf16.h>
#include <cstdint>

#define N_NODES 65536
#define N_EDGES 1048576
#define IN_F 64
#define OUT_F 64

#define SCAN_BLOCKS 64          // 64 blocks x 256 threads x 4 counts = 65536

// ---- scratch (static __device__, 16B-aligned, no allocation) ----
__device__ __align__(16) float g_support[(size_t)N_NODES * OUT_F];  // 16 MB
__device__ __align__(16) uint2 g_sorted[N_EDGES + 8];               // 8 MB + pad
__device__ __align__(16) int   g_counts[N_NODES];
__device__ __align__(16) int   g_rowptr[N_NODES];
__device__ __align__(16) int   g_cursor[N_NODES];
__device__ __align__(16) int   g_blocksums[SCAN_BLOCKS];

// ---------------------------------------------------------------------------
// support = X @ W   (one thread per row, W broadcast from smem)
// ---------------------------------------------------------------------------
__global__ void __launch_bounds__(256)
gemm_kernel(const float* __restrict__ X, const float* __restrict__ W,
            float* __restrict__ S, int n_nodes)
{
    __shared__ float sW[IN_F * OUT_F];
    for (int i = threadIdx.x; i < IN_F * OUT_F; i += 256)
        sW[i] = W[i];
    __syncthreads();

    int row = blockIdx.x * 256 + threadIdx.x;
    if (row >= n_nodes) return;

    float acc[OUT_F];
#pragma unroll
    for (int j = 0; j < OUT_F; j++) acc[j] = 0.0f;

    const float4* xr = reinterpret_cast<const float4*>(X + (size_t)row * IN_F);
#pragma unroll 4
    for (int k4 = 0; k4 < IN_F / 4; k4++) {
        float4 x = xr[k4];
        int k = k4 * 4;
        const float4* w0 = reinterpret_cast<const float4*>(sW + (k + 0) * OUT_F);
        const float4* w1 = reinterpret_cast<const float4*>(sW + (k + 1) * OUT_F);
        const float4* w2 = reinterpret_cast<const float4*>(sW + (k + 2) * OUT_F);
        const float4* w3 = reinterpret_cast<const float4*>(sW + (k + 3) * OUT_F);
#pragma unroll
        for (int j4 = 0; j4 < OUT_F / 4; j4++) {
            float4 a = w0[j4], b = w1[j4], c = w2[j4], d = w3[j4];
            acc[j4 * 4 + 0] += x.x * a.x + x.y * b.x + x.z * c.x + x.w * d.x;
            acc[j4 * 4 + 1] += x.x * a.y + x.y * b.y + x.z * c.y + x.w * d.y;
            acc[j4 * 4 + 2] += x.x * a.z + x.y * b.z + x.z * c.z + x.w * d.z;
            acc[j4 * 4 + 3] += x.x * a.w + x.y * b.w + x.z * c.w + x.w * d.w;
        }
    }

    float4* sr = reinterpret_cast<float4*>(S + (size_t)row * OUT_F);
#pragma unroll
    for (int j4 = 0; j4 < OUT_F / 4; j4++)
        sr[j4] = make_float4(acc[j4*4+0], acc[j4*4+1], acc[j4*4+2], acc[j4*4+3]);
}

// ---------------------------------------------------------------------------
// zero degree counters (also zeroes the sorted-array pad once per call)
// ---------------------------------------------------------------------------
__global__ void __launch_bounds__(256)
zero_counts_kernel(int* __restrict__ counts, uint2* __restrict__ sorted_pad,
                   int n)
{
    int i = blockIdx.x * 256 + threadIdx.x;
    if (i < n) counts[i] = 0;
    if (blockIdx.x == 0 && threadIdx.x < 8)
        sorted_pad[threadIdx.x] = make_uint2(0u, 0u);
}

// ---------------------------------------------------------------------------
// histogram of destination rows
// ---------------------------------------------------------------------------
__global__ void __launch_bounds__(256)
hist_kernel(const int* __restrict__ rows, int* __restrict__ counts, int n_edges)
{
    int e = blockIdx.x * 256 + threadIdx.x;
    if (e < n_edges) atomicAdd(&counts[rows[e]], 1);
}

// ---------------------------------------------------------------------------
// scan phase A: 64 blocks; each reduces its 1024 counts to one block sum
// ---------------------------------------------------------------------------
__global__ void __launch_bounds__(256)
scan_a_kernel(const int* __restrict__ counts, int* __restrict__ blocksums)
{
    __shared__ int sred[256];
    int t = threadIdx.x;
    int4 c = reinterpret_cast<const int4*>(counts)[blockIdx.x * 256 + t];
    int s = c.x + c.y + c.z + c.w;
    sred[t] = s;
    __syncthreads();
    for (int d = 128; d > 0; d >>= 1) {
        if (t < d) sred[t] += sred[t + d];
        __syncthreads();
    }
    if (t == 0) blocksums[blockIdx.x] = sred[0];
}

// ---------------------------------------------------------------------------
// scan phase C (B folded in): each block computes its global offset from the
// 64 L2-resident block sums, then block-local exclusive scan; emits
// rowptr and cursor.
// ---------------------------------------------------------------------------
__global__ void __launch_bounds__(256)
scan_c_kernel(const int* __restrict__ counts, const int* __restrict__ blocksums,
              int* __restrict__ rowptr, int* __restrict__ cursor)
{
    __shared__ int ssum[256];
    __shared__ int sboff;
    int t = threadIdx.x;
    int gidx = blockIdx.x * 256 + t;

    // fold scan_b: sum of blocksums[0..bid) via in-block reduction
    int part = (t < 64 && t < blockIdx.x) ? blocksums[t] : 0;
    ssum[t] = part;
    __syncthreads();
    for (int d = 128; d > 0; d >>= 1) {
        if (t < d) ssum[t] += ssum[t + d];
        __syncthreads();
    }
    if (t == 0) sboff = ssum[0];
    __syncthreads();
    int boff = sboff;
    __syncthreads();

    int4 c = reinterpret_cast<const int4*>(counts)[gidx];
    int s = c.x + c.y + c.z + c.w;
    ssum[t] = s;
    __syncthreads();
    for (int d = 1; d < 256; d <<= 1) {
        int add = (t >= d) ? ssum[t - d] : 0;
        __syncthreads();
        ssum[t] += add;
        __syncthreads();
    }
    int run = boff + ssum[t] - s;  // global exclusive prefix

    int4 o;
    o.x = run; run += c.x;
    o.y = run; run += c.y;
    o.z = run; run += c.z;
    o.w = run; run += c.w;
    reinterpret_cast<int4*>(rowptr)[gidx] = o;
    reinterpret_cast<int4*>(cursor)[gidx] = o;
}

// ---------------------------------------------------------------------------
// place each edge into its dest bucket (cursor-atomic, proven)
// ---------------------------------------------------------------------------
__global__ void __launch_bounds__(256)
place_kernel(const int* __restrict__ rows, const int* __restrict__ cols,
             const float* __restrict__ vals, int* __restrict__ cursor,
             uint2* __restrict__ sorted, int n_edges)
{
    int e = blockIdx.x * 256 + threadIdx.x;
    if (e >= n_edges) return;
    int r = rows[e];
    int pos = atomicAdd(&cursor[r], 1);
    sorted[pos] = make_uint2((unsigned)cols[e], __float_as_uint(vals[e]));
}

// ---------------------------------------------------------------------------
// Gather v5: ONE WARP PER NODE, paired-row LDG.128 gathers.
// Each gather instruction fetches TWO edges' support rows: lanes 0-15 read
// edge-A's 256B row (16B each), lanes 16-31 read edge-B's. 4 such loads in
// flight = 8 edges per iteration at ~16 regs of gather state. Final
// shfl_xor(16) folds the two half-warp accumulators; lanes 0-15 write the
// output row. Hardened: col masked with N_NODES-1, start/deg clamped,
// padded slots contribute v=0.
// ---------------------------------------------------------------------------
__global__ void __launch_bounds__(256)
gather_kernel(const int* __restrict__ rowptr, const int* __restrict__ counts,
              const uint2* __restrict__ sorted, const float* __restrict__ S,
              const float* __restrict__ bias, float* __restrict__ out,
              int n_nodes)
{
    int node = (blockIdx.x * 256 + threadIdx.x) >> 5;
    if (node >= n_nodes) return;
    int lane = threadIdx.x & 31;
    int half = lane >> 4;         // 0: even-slot edge, 1: odd-slot edge
    int l16  = lane & 15;         // 16B chunk within the 256B row

    int start = rowptr[node];
    int deg   = counts[node];

    // defensive clamps: gather can never read outside sorted[] / S[]
    if (start < 0) start = 0;
    if (start > N_EDGES) start = N_EDGES;
    if (deg < 0) deg = 0;
    if (deg > N_EDGES - start) deg = N_EDGES - start;

    const uint2*  ep = sorted + start;
    const float4* S4 = reinterpret_cast<const float4*>(S);

    float4 acc = make_float4(0.f, 0.f, 0.f, 0.f);
    int nb = (deg + 7) >> 3;      // 8 edges per iteration (4 paired gathers)

    uint2 a[8];
#pragma unroll
    for (int i = 0; i < 8; i++)
        a[i] = (i < deg) ? ep[i] : make_uint2(0u, 0u);

    for (int b = 0; b < nb; b++) {
        // 4 paired LDG.128 gathers: each covers 2 edges (one per half-warp)
#pragma unroll
        for (int g = 0; g < 4; g++) {
            uint2 e_lo = a[2 * g + 0];
            uint2 e_hi = a[2 * g + 1];
            unsigned row = (half ? e_hi.x : e_lo.x) & (N_NODES - 1);
            float4 s = S4[(size_t)row * 16 + l16];
            float v = __uint_as_float(half ? e_hi.y : e_lo.y);
            acc.x += v * s.x;
            acc.y += v * s.y;
            acc.z += v * s.z;
            acc.w += v * s.w;
        }

        // prefetch next 8 edge records (warp-uniform broadcast loads)
        int nxt = (b + 1) * 8;
        uint2 n8[8];
#pragma unroll
        for (int i = 0; i < 8; i++)
            n8[i] = (nxt + i < deg) ? ep[nxt + i] : make_uint2(0u, 0u);
#pragma unroll
        for (int i = 0; i < 8; i++) a[i] = n8[i];
    }

    // fold the two half-warp accumulators (features 4*l16 .. 4*l16+3)
    acc.x += __shfl_xor_sync(0xFFFFFFFFu, acc.x, 16);
    acc.y += __shfl_xor_sync(0xFFFFFFFFu, acc.y, 16);
    acc.z += __shfl_xor_sync(0xFFFFFFFFu, acc.z, 16);
    acc.w += __shfl_xor_sync(0xFFFFFFFFu, acc.w, 16);

    if (half == 0) {
        float4 bb = reinterpret_cast<const float4*>(bias)[l16];
        float4 r;
        r.x = fmaxf(acc.x + bb.x, 0.f);
        r.y = fmaxf(acc.y + bb.y, 0.f);
        r.z = fmaxf(acc.z + bb.z, 0.f);
        r.w = fmaxf(acc.w + bb.w, 0.f);
        reinterpret_cast<float4*>(out)[(size_t)node * 16 + l16] = r;
    }
}

extern "C" void kernel_launch(void* const* d_in, const int* in_sizes, int n_in,
                              void* d_out, int out_size)
{
    const float* X    = (const float*)d_in[0];
    const int*   rows = (const int*)  d_in[1];
    const int*   cols = (const int*)  d_in[2];
    const float* vals = (const float*)d_in[3];
    const float* W    = (const float*)d_in[4];
    const float* bias = (const float*)d_in[5];
    float*       out  = (float*)d_out;

    int n_nodes = in_sizes[0] / IN_F;
    int n_edges = in_sizes[1];

    float* S;      cudaGetSymbolAddress((void**)&S,      g_support);
    uint2* sorted; cudaGetSymbolAddress((void**)&sorted, g_sorted);
    int*   counts; cudaGetSymbolAddress((void**)&counts, g_counts);
    int*   rowptr; cudaGetSymbolAddress((void**)&rowptr, g_rowptr);
    int*   cursor; cudaGetSymbolAddress((void**)&cursor, g_cursor);
    int*   bsums;  cudaGetSymbolAddress((void**)&bsums,  g_blocksums);

    // Side stream + events for gemm overlap (capture-legal fork/join).
    static cudaStream_t s_gemm = nullptr;
    static cudaEvent_t  ev_fork = nullptr, ev_done = nullptr;
    if (s_gemm == nullptr) {
        cudaStreamCreateWithFlags(&s_gemm, cudaStreamNonBlocking);
        cudaEventCreateWithFlags(&ev_fork, cudaEventDisableTiming);
        cudaEventCreateWithFlags(&ev_done, cudaEventDisableTiming);
    }

    // Fork: gemm on the side stream, overlapped with the CSR build.
    cudaEventRecord(ev_fork, 0);
    cudaStreamWaitEvent(s_gemm, ev_fork, 0);
    gemm_kernel<<<(n_nodes + 255) / 256, 256, 0, s_gemm>>>(X, W, S, n_nodes);
    cudaEventRecord(ev_done, s_gemm);

    // CSR build on the main stream.
    zero_counts_kernel<<<(n_nodes + 255) / 256, 256>>>(counts, sorted + N_EDGES,
                                                       n_nodes);
    hist_kernel<<<(n_edges + 255) / 256, 256>>>(rows, counts, n_edges);
    scan_a_kernel<<<SCAN_BLOCKS, 256>>>(counts, bsums);
    scan_c_kernel<<<SCAN_BLOCKS, 256>>>(counts, bsums, rowptr, cursor);
    place_kernel<<<(n_edges + 255) / 256, 256>>>(rows, cols, vals, cursor,
                                                 sorted, n_edges);

    // Join: gather needs both the CSR and the support matrix.
    cudaStreamWaitEvent(0, ev_done, 0);
    long long total = (long long)n_nodes * 32;
    gather_kernel<<<(int)((total + 255) / 256), 256>>>(rowptr, counts, sorted,
                                                       S, bias, out, n_nodes);
}